// round 5
// baseline (speedup 1.0000x reference)
#include <cuda_runtime.h>
#include <cuda_bf16.h>
#include <cstdint>
#include <math.h>

#define NTOK 4096
#define DIM  1024
#define HID  4096
#define NEXP 8
#define MAXA (NTOK * 2)

// ---------------- device scratch (static, allocation-free) ----------------
__device__ int   g_cnt[NEXP];
__device__ int   g_list[NEXP][MAXA];
__device__ float g_wgt[MAXA];
__device__ __nv_bfloat16 g_x_hi[(size_t)NTOK * DIM];
__device__ __nv_bfloat16 g_x_lo[(size_t)NTOK * DIM];
__device__ __nv_bfloat16 g_w1_hi[(size_t)NEXP * HID * DIM];   // [e][h][d]
__device__ __nv_bfloat16 g_w1_lo[(size_t)NEXP * HID * DIM];
__device__ __nv_bfloat16 g_w2_hi[(size_t)NEXP * DIM * HID];   // [e][d][h]
__device__ __nv_bfloat16 g_w2_lo[(size_t)NEXP * DIM * HID];
__device__ __nv_bfloat16 g_h_hi[(size_t)MAXA * HID];
__device__ __nv_bfloat16 g_h_lo[(size_t)MAXA * HID];

// ---------------- helpers ----------------
__device__ __forceinline__ uint32_t smem_u32(const void* p) {
    uint32_t a;
    asm("{ .reg .u64 t; cvta.to.shared.u64 t, %1; cvt.u32.u64 %0, t; }" : "=r"(a) : "l"(p));
    return a;
}
__device__ __forceinline__ void cp16(uint32_t dst, const void* src, uint32_t srcsz) {
    asm volatile("cp.async.cg.shared.global [%0], [%1], 16, %2;"
                 :: "r"(dst), "l"(src), "r"(srcsz) : "memory");
}
#define CP_COMMIT() asm volatile("cp.async.commit_group;" ::: "memory")
#define CP_WAIT(n)  asm volatile("cp.async.wait_group %0;" :: "n"(n) : "memory")

__device__ __forceinline__ void ldsm4(uint32_t* r, uint32_t addr) {
    asm volatile("ldmatrix.sync.aligned.m8n8.x4.shared.b16 {%0,%1,%2,%3}, [%4];"
                 : "=r"(r[0]), "=r"(r[1]), "=r"(r[2]), "=r"(r[3]) : "r"(addr));
}
__device__ __forceinline__ void mma16816(float* c, const uint32_t* a, uint32_t b0, uint32_t b1) {
    asm volatile(
        "mma.sync.aligned.m16n8k16.row.col.f32.bf16.bf16.f32 "
        "{%0,%1,%2,%3}, {%4,%5,%6,%7}, {%8,%9}, {%0,%1,%2,%3};"
        : "+f"(c[0]), "+f"(c[1]), "+f"(c[2]), "+f"(c[3])
        : "r"(a[0]), "r"(a[1]), "r"(a[2]), "r"(a[3]), "r"(b0), "r"(b1));
}
__device__ __forceinline__ uint32_t pack_bf2(float a, float b) {
    __nv_bfloat162 t = __floats2bfloat162_rn(a, b);
    return *reinterpret_cast<uint32_t*>(&t);
}
#define SWZ(o) ((o) ^ (((o) >> 3) & 0x70))

// ---------------- phase 0: zero out + counters ----------------
__global__ void zero_kernel(float* __restrict__ out) {
    size_t i = ((size_t)blockIdx.x * blockDim.x + threadIdx.x) * 4;
    if (i < (size_t)NTOK * DIM)
        *reinterpret_cast<float4*>(out + i) = make_float4(0.f, 0.f, 0.f, 0.f);
    if (blockIdx.x == 0 && threadIdx.x < NEXP) g_cnt[threadIdx.x] = 0;
}

// ---------------- split-convert x -> bf16 hi/lo ----------------
__global__ void conv_x(const float* __restrict__ x) {
    size_t i = ((size_t)blockIdx.x * blockDim.x + threadIdx.x) * 8;
    float v[8];
    *reinterpret_cast<float4*>(v)     = *reinterpret_cast<const float4*>(x + i);
    *reinterpret_cast<float4*>(v + 4) = *reinterpret_cast<const float4*>(x + i + 4);
    uint32_t ph[4], pl[4];
#pragma unroll
    for (int j = 0; j < 4; j++) {
        float a = v[2 * j], b = v[2 * j + 1];
        __nv_bfloat16 ha = __float2bfloat16(a), hb = __float2bfloat16(b);
        ph[j] = pack_bf2(a, b);
        pl[j] = pack_bf2(a - __bfloat162float(ha), b - __bfloat162float(hb));
    }
    *reinterpret_cast<uint4*>(g_x_hi + i) = make_uint4(ph[0], ph[1], ph[2], ph[3]);
    *reinterpret_cast<uint4*>(g_x_lo + i) = make_uint4(pl[0], pl[1], pl[2], pl[3]);
}

// ------- transpose-convert W [e][R][C] -> [e][C][R] bf16 hi/lo (packed stores) -------
__global__ void conv_w(const float* __restrict__ src, __nv_bfloat16* __restrict__ dh,
                       __nv_bfloat16* __restrict__ dl, int R, int C) {
    __shared__ float t[32][33];
    int e  = blockIdx.z;
    int r0 = blockIdx.y * 32, c0 = blockIdx.x * 32;
    int tx = threadIdx.x;   // 0..15
    int ty = threadIdx.y;   // 0..15
    const float* sp = src + (size_t)e * R * C;
#pragma unroll
    for (int j = 0; j < 2; j++) {
        int r = ty + 16 * j;
        float2 v = *reinterpret_cast<const float2*>(sp + (size_t)(r0 + r) * C + c0 + 2 * tx);
        t[r][2 * tx]     = v.x;
        t[r][2 * tx + 1] = v.y;
    }
    __syncthreads();
#pragma unroll
    for (int j = 0; j < 2; j++) {
        int cc = ty + 16 * j;
        float v0 = t[2 * tx][cc], v1 = t[2 * tx + 1][cc];
        __nv_bfloat16 h0 = __float2bfloat16(v0), h1 = __float2bfloat16(v1);
        size_t o = ((size_t)e * C + c0 + cc) * R + r0 + 2 * tx;
        *reinterpret_cast<uint32_t*>(dh + o) = pack_bf2(v0, v1);
        *reinterpret_cast<uint32_t*>(dl + o) =
            pack_bf2(v0 - __bfloat162float(h0), v1 - __bfloat162float(h1));
    }
}

// ---------------- gating (1 warp / token) ----------------
__global__ void gating_kernel(const float* __restrict__ x,
                              const float* __restrict__ Wg,
                              const float* __restrict__ bg) {
    int tok  = (blockIdx.x * blockDim.x + threadIdx.x) >> 5;
    int lane = threadIdx.x & 31;
    if (tok >= NTOK) return;
    const float* xr = x + (size_t)tok * DIM;
    float acc[NEXP];
#pragma unroll
    for (int e = 0; e < NEXP; e++) acc[e] = 0.f;
    for (int d = lane; d < DIM; d += 32) {
        float xv = xr[d];
        const float* wr = Wg + d * NEXP;
#pragma unroll
        for (int e = 0; e < NEXP; e++) acc[e] += xv * wr[e];
    }
#pragma unroll
    for (int off = 16; off; off >>= 1)
#pragma unroll
        for (int e = 0; e < NEXP; e++)
            acc[e] += __shfl_xor_sync(0xffffffffu, acc[e], off);
    if (lane == 0) {
        float logit[NEXP], m = -1e30f;
#pragma unroll
        for (int e = 0; e < NEXP; e++) { logit[e] = acc[e] + bg[e]; m = fmaxf(m, logit[e]); }
        float p[NEXP], s = 0.f;
#pragma unroll
        for (int e = 0; e < NEXP; e++) { p[e] = expf(logit[e] - m); s += p[e]; }
        float inv = 1.f / s;
#pragma unroll
        for (int e = 0; e < NEXP; e++) p[e] *= inv;
        int e0 = 0;
#pragma unroll
        for (int e = 1; e < NEXP; e++) if (p[e] > p[e0]) e0 = e;
        int e1 = (e0 == 0) ? 1 : 0;
#pragma unroll
        for (int e = 0; e < NEXP; e++) if (e != e0 && p[e] > p[e1]) e1 = e;
        g_wgt[2 * tok + 0] = p[e0];
        g_wgt[2 * tok + 1] = p[e1];
        int p0 = atomicAdd(&g_cnt[e0], 1); g_list[e0][p0] = 2 * tok + 0;
        int p1 = atomicAdd(&g_cnt[e1], 1); g_list[e1][p1] = 2 * tok + 1;
    }
}

// ---------------- HMMA split-bf16 gathered GEMM ----------------
// CTA 128x128, 256 thr, warps 4(m) x 2(n), K-chunk 32, 3-stage cp.async
// pipeline (prefetch distance 2), 32KB/stage, 96KB total -> 2 CTAs/SM.
// Stage row layout (128B, SW128 swizzled): [hi 32xbf16 | lo 32xbf16].
template <bool PHASE1>
__global__ void __launch_bounds__(256, 2)
moe_gemm(const float* __restrict__ bias, float* __restrict__ out) {
    constexpr int KD  = PHASE1 ? DIM : HID;
    constexpr int ND  = PHASE1 ? HID : DIM;
    constexpr int NCH = KD / 32;
    constexpr int STG = 32 * 1024;    // per stage: A 16KB + B 16KB

    const __nv_bfloat16* Ah = PHASE1 ? g_x_hi : g_h_hi;
    const __nv_bfloat16* Al = PHASE1 ? g_x_lo : g_h_lo;
    const __nv_bfloat16* Bh = PHASE1 ? g_w1_hi : g_w2_hi;
    const __nv_bfloat16* Bl = PHASE1 ? g_w1_lo : g_w2_lo;

    const int e   = blockIdx.z;
    const int cnt = g_cnt[e];
    const int m0  = blockIdx.y * 128;
    if (m0 >= cnt) return;
    const int n0  = blockIdx.x * 128;
    const int tid = threadIdx.x;

    extern __shared__ char smraw[];
    char* tilep = (char*)(((uintptr_t)smraw + 1023) & ~(uintptr_t)1023);
    const uint32_t sbase = smem_u32(tilep);
    __shared__ float s_bias[128];
    if (tid < 128) s_bias[tid] = bias[(size_t)e * ND + n0 + tid];

    // ---- load mapping: seg 0-3 = hi 8-elem groups, seg 4-7 = lo ----
    const int seg   = tid & 7;
    const int ks    = (seg & 3) * 8;      // k element offset within chunk
    const bool lowp = seg >= 4;
    const int rg    = tid >> 3;           // 0..31, rows rg + 32p
    const __nv_bfloat16* Asrc = lowp ? Al : Ah;
    const __nv_bfloat16* Bsrc = lowp ? Bl : Bh;
    size_t   aoff[4], boff[4];
    uint32_t avalid[4], swzo[4];
#pragma unroll
    for (int p = 0; p < 4; p++) {
        int r   = rg + 32 * p;
        int idx = m0 + r;
        int a   = (idx < cnt) ? g_list[e][idx] : 0;
        int ra  = PHASE1 ? (a >> 1) : a;
        avalid[p] = (idx < cnt) ? 16u : 0u;
        aoff[p]   = (size_t)ra * KD + ks;
        boff[p]   = ((size_t)e * ND + n0 + r) * KD + ks;
        swzo[p]   = SWZ(r * 128 + seg * 16);
    }

    // ---- fragment addressing ----
    const int lane = tid & 31;
    const int wid  = tid >> 5;
    const int wm   = wid >> 1;        // 0..3
    const int wn   = wid & 1;         // 0..1
    uint32_t abase[2], axor[2], bbase[4], bxor[4];
#pragma unroll
    for (int mf = 0; mf < 2; mf++) {
        int row   = wm * 32 + mf * 16 + (lane & 15);
        abase[mf] = row * 128 + (lane >> 4) * 16;
        axor[mf]  = (row & 7) << 4;
    }
#pragma unroll
    for (int p = 0; p < 4; p++) {
        int row  = wn * 64 + p * 16 + (lane & 15);
        bbase[p] = row * 128 + (lane >> 4) * 16;
        bxor[p]  = (row & 7) << 4;
    }

    float acc[2][8][4];
#pragma unroll
    for (int i = 0; i < 2; i++)
#pragma unroll
        for (int j = 0; j < 8; j++)
#pragma unroll
            for (int q = 0; q < 4; q++) acc[i][j][q] = 0.f;

#define ISSUE_CHUNK(CC, BUF) do {                                              \
        const size_t _ko = (size_t)(CC) * 32;                                  \
        uint32_t _sb = sbase + (BUF) * STG;                                    \
        _Pragma("unroll")                                                      \
        for (int p = 0; p < 4; p++) {                                          \
            cp16(_sb + swzo[p],         Asrc + aoff[p] + _ko, avalid[p]);      \
            cp16(_sb + 16384 + swzo[p], Bsrc + boff[p] + _ko, 16u);            \
        }                                                                      \
        CP_COMMIT();                                                           \
    } while (0)

    // ---- prologue: chunks 0,1 ----
    ISSUE_CHUNK(0, 0);
    ISSUE_CHUNK(1, 1);

    int bufc = 0;   // buffer holding chunk c
    int bufl = 2;   // buffer to load into
    for (int c = 0; c < NCH; ++c) {
        if (c + 2 < NCH) {
            ISSUE_CHUNK(c + 2, bufl);
            CP_WAIT(2);
        } else if (c + 1 < NCH) {
            CP_WAIT(1);
        } else {
            CP_WAIT(0);
        }
        __syncthreads();

        const uint32_t sb = sbase + bufc * STG;
#pragma unroll
        for (int kk = 0; kk < 2; kk++) {
            uint32_t ah[2][4], al[2][4], bh[4][4], bl[4][4];
#pragma unroll
            for (int mf = 0; mf < 2; mf++) {
                ldsm4(ah[mf], sb + ((abase[mf] + kk * 32) ^ axor[mf]));
                ldsm4(al[mf], sb + ((abase[mf] + 64 + kk * 32) ^ axor[mf]));
            }
#pragma unroll
            for (int p = 0; p < 4; p++) {
                ldsm4(bh[p], sb + 16384 + ((bbase[p] + kk * 32) ^ bxor[p]));
                ldsm4(bl[p], sb + 16384 + ((bbase[p] + 64 + kk * 32) ^ bxor[p]));
            }
            // term 1: Ah * Bh
#pragma unroll
            for (int mf = 0; mf < 2; mf++)
#pragma unroll
                for (int p = 0; p < 4; p++) {
                    mma16816(acc[mf][2 * p],     ah[mf], bh[p][0], bh[p][2]);
                    mma16816(acc[mf][2 * p + 1], ah[mf], bh[p][1], bh[p][3]);
                }
            // term 2: Ah * Bl
#pragma unroll
            for (int mf = 0; mf < 2; mf++)
#pragma unroll
                for (int p = 0; p < 4; p++) {
                    mma16816(acc[mf][2 * p],     ah[mf], bl[p][0], bl[p][2]);
                    mma16816(acc[mf][2 * p + 1], ah[mf], bl[p][1], bl[p][3]);
                }
            // term 3: Al * Bh
#pragma unroll
            for (int mf = 0; mf < 2; mf++)
#pragma unroll
                for (int p = 0; p < 4; p++) {
                    mma16816(acc[mf][2 * p],     al[mf], bh[p][0], bh[p][2]);
                    mma16816(acc[mf][2 * p + 1], al[mf], bh[p][1], bh[p][3]);
                }
        }
        __syncthreads();

        bufc = (bufc == 2) ? 0 : bufc + 1;
        bufl = (bufl == 2) ? 0 : bufl + 1;
    }
#undef ISSUE_CHUNK

    // ---- epilogue ----
    const int quad  = lane >> 2;
    const int qid   = lane & 3;
    const int ncol0 = wn * 64;

#pragma unroll
    for (int mf = 0; mf < 2; mf++) {
#pragma unroll
        for (int rv = 0; rv < 2; rv++) {
            int midx = m0 + wm * 32 + mf * 16 + rv * 8 + quad;
            if (midx >= cnt) continue;
            int a = g_list[e][midx];
            if (PHASE1) {
                __nv_bfloat16* dh = g_h_hi + (size_t)a * HID + n0;
                __nv_bfloat16* dl = g_h_lo + (size_t)a * HID + n0;
#pragma unroll
                for (int nf = 0; nf < 8; nf++) {
                    int nloc = ncol0 + nf * 8 + 2 * qid;
                    float v0 = fmaxf(acc[mf][nf][2 * rv]     + s_bias[nloc],     0.f);
                    float v1 = fmaxf(acc[mf][nf][2 * rv + 1] + s_bias[nloc + 1], 0.f);
                    __nv_bfloat16 h0 = __float2bfloat16(v0), h1 = __float2bfloat16(v1);
                    *reinterpret_cast<uint32_t*>(dh + nloc) = pack_bf2(v0, v1);
                    *reinterpret_cast<uint32_t*>(dl + nloc) =
                        pack_bf2(v0 - __bfloat162float(h0), v1 - __bfloat162float(h1));
                }
            } else {
                float w = g_wgt[a];
                float* op = out + (size_t)(a >> 1) * DIM + n0;
#pragma unroll
                for (int nf = 0; nf < 8; nf++) {
                    int nloc = ncol0 + nf * 8 + 2 * qid;
                    atomicAdd(op + nloc,     (acc[mf][nf][2 * rv]     + s_bias[nloc])     * w);
                    atomicAdd(op + nloc + 1, (acc[mf][nf][2 * rv + 1] + s_bias[nloc + 1]) * w);
                }
            }
        }
    }
}

// ---------------- launch ----------------
extern "C" void kernel_launch(void* const* d_in, const int* in_sizes, int n_in,
                              void* d_out, int out_size) {
    const float* x  = (const float*)d_in[0];
    const float* Wg = (const float*)d_in[1];
    const float* bg = (const float*)d_in[2];
    const float* W1 = (const float*)d_in[3];
    const float* b1 = (const float*)d_in[4];
    const float* W2 = (const float*)d_in[5];
    const float* b2 = (const float*)d_in[6];
    float* out = (float*)d_out;

    const int SMEM_BYTES = 3 * 32 * 1024 + 1024;
    cudaFuncSetAttribute((const void*)moe_gemm<true>,
                         cudaFuncAttributeMaxDynamicSharedMemorySize, SMEM_BYTES);
    cudaFuncSetAttribute((const void*)moe_gemm<false>,
                         cudaFuncAttributeMaxDynamicSharedMemorySize, SMEM_BYTES);

    __nv_bfloat16 *w1h, *w1l, *w2h, *w2l;
    cudaGetSymbolAddress((void**)&w1h, g_w1_hi);
    cudaGetSymbolAddress((void**)&w1l, g_w1_lo);
    cudaGetSymbolAddress((void**)&w2h, g_w2_hi);
    cudaGetSymbolAddress((void**)&w2l, g_w2_lo);

    zero_kernel<<<(NTOK * DIM) / (256 * 4), 256>>>(out);
    conv_x<<<(NTOK * DIM) / (256 * 8), 256>>>(x);
    conv_w<<<dim3(HID / 32, DIM / 32, NEXP), dim3(16, 16)>>>(W1, w1h, w1l, DIM, HID);
    conv_w<<<dim3(DIM / 32, HID / 32, NEXP), dim3(16, 16)>>>(W2, w2h, w2l, HID, DIM);
    gating_kernel<<<(NTOK * 32) / 256, 256>>>(x, Wg, bg);

    moe_gemm<true><<<dim3(HID / 128, MAXA / 128, NEXP), 256, SMEM_BYTES>>>(b1, nullptr);
    moe_gemm<false><<<dim3(DIM / 128, MAXA / 128, NEXP), 256, SMEM_BYTES>>>(b2, out);
}

// round 6
// speedup vs baseline: 1.6404x; 1.6404x over previous
#include <cuda_runtime.h>
#include <cuda_fp16.h>
#include <cstdint>
#include <math.h>

#define NTOK 4096
#define DIM  1024
#define HID  4096
#define NEXP 8
#define MAXA (NTOK * 2)

// ---------------- device scratch (static, allocation-free) ----------------
__device__ int   g_cnt[NEXP];
__device__ int   g_list[NEXP][MAXA];
__device__ float g_wgt[MAXA];
__device__ __half g_x[(size_t)NTOK * DIM];
__device__ __half g_w1_hi[(size_t)NEXP * HID * DIM];   // [e][h][d]
__device__ __half g_w1_lo[(size_t)NEXP * HID * DIM];
__device__ __half g_w2_hi[(size_t)NEXP * DIM * HID];   // [e][d][h]
__device__ __half g_w2_lo[(size_t)NEXP * DIM * HID];
__device__ __half g_h[(size_t)MAXA * HID];

// ---------------- helpers ----------------
__device__ __forceinline__ uint32_t smem_u32(const void* p) {
    uint32_t a;
    asm("{ .reg .u64 t; cvta.to.shared.u64 t, %1; cvt.u32.u64 %0, t; }" : "=r"(a) : "l"(p));
    return a;
}
__device__ __forceinline__ void cp16(uint32_t dst, const void* src, uint32_t srcsz) {
    asm volatile("cp.async.cg.shared.global [%0], [%1], 16, %2;"
                 :: "r"(dst), "l"(src), "r"(srcsz) : "memory");
}
#define CP_COMMIT() asm volatile("cp.async.commit_group;" ::: "memory")
#define CP_WAIT(n)  asm volatile("cp.async.wait_group %0;" :: "n"(n) : "memory")

__device__ __forceinline__ void ldsm4(uint32_t* r, uint32_t addr) {
    asm volatile("ldmatrix.sync.aligned.m8n8.x4.shared.b16 {%0,%1,%2,%3}, [%4];"
                 : "=r"(r[0]), "=r"(r[1]), "=r"(r[2]), "=r"(r[3]) : "r"(addr));
}
__device__ __forceinline__ void mma16816(float* c, const uint32_t* a, uint32_t b0, uint32_t b1) {
    asm volatile(
        "mma.sync.aligned.m16n8k16.row.col.f32.f16.f16.f32 "
        "{%0,%1,%2,%3}, {%4,%5,%6,%7}, {%8,%9}, {%0,%1,%2,%3};"
        : "+f"(c[0]), "+f"(c[1]), "+f"(c[2]), "+f"(c[3])
        : "r"(a[0]), "r"(a[1]), "r"(a[2]), "r"(a[3]), "r"(b0), "r"(b1));
}
__device__ __forceinline__ uint32_t pack_h2(float a, float b) {
    __half2 t = __floats2half2_rn(a, b);
    return *reinterpret_cast<uint32_t*>(&t);
}
#define SWZ(o) ((o) ^ (((o) >> 3) & 0x70))

// ---------------- phase 0: zero out + counters ----------------
__global__ void zero_kernel(float* __restrict__ out) {
    size_t i = ((size_t)blockIdx.x * blockDim.x + threadIdx.x) * 4;
    if (i < (size_t)NTOK * DIM)
        *reinterpret_cast<float4*>(out + i) = make_float4(0.f, 0.f, 0.f, 0.f);
    if (blockIdx.x == 0 && threadIdx.x < NEXP) g_cnt[threadIdx.x] = 0;
}

// ---------------- convert x -> fp16 ----------------
__global__ void conv_x(const float* __restrict__ x) {
    size_t i = ((size_t)blockIdx.x * blockDim.x + threadIdx.x) * 8;
    float v[8];
    *reinterpret_cast<float4*>(v)     = *reinterpret_cast<const float4*>(x + i);
    *reinterpret_cast<float4*>(v + 4) = *reinterpret_cast<const float4*>(x + i + 4);
    uint32_t p[4];
#pragma unroll
    for (int j = 0; j < 4; j++) p[j] = pack_h2(v[2 * j], v[2 * j + 1]);
    *reinterpret_cast<uint4*>(g_x + i) = make_uint4(p[0], p[1], p[2], p[3]);
}

// ------- transpose-convert W [e][R][C] -> [e][C][R] fp16 hi/lo (packed stores) -------
__global__ void conv_w(const float* __restrict__ src, __half* __restrict__ dh,
                       __half* __restrict__ dl, int R, int C) {
    __shared__ float t[32][33];
    int e  = blockIdx.z;
    int r0 = blockIdx.y * 32, c0 = blockIdx.x * 32;
    int tx = threadIdx.x;   // 0..15
    int ty = threadIdx.y;   // 0..15
    const float* sp = src + (size_t)e * R * C;
#pragma unroll
    for (int j = 0; j < 2; j++) {
        int r = ty + 16 * j;
        float2 v = *reinterpret_cast<const float2*>(sp + (size_t)(r0 + r) * C + c0 + 2 * tx);
        t[r][2 * tx]     = v.x;
        t[r][2 * tx + 1] = v.y;
    }
    __syncthreads();
#pragma unroll
    for (int j = 0; j < 2; j++) {
        int cc = ty + 16 * j;
        float v0 = t[2 * tx][cc], v1 = t[2 * tx + 1][cc];
        __half h0 = __float2half_rn(v0), h1 = __float2half_rn(v1);
        size_t o = ((size_t)e * C + c0 + cc) * R + r0 + 2 * tx;
        *reinterpret_cast<uint32_t*>(dh + o) = pack_h2(v0, v1);
        *reinterpret_cast<uint32_t*>(dl + o) =
            pack_h2(v0 - __half2float(h0), v1 - __half2float(h1));
    }
}

// ---------------- gating (1 warp / token) ----------------
__global__ void gating_kernel(const float* __restrict__ x,
                              const float* __restrict__ Wg,
                              const float* __restrict__ bg) {
    int tok  = (blockIdx.x * blockDim.x + threadIdx.x) >> 5;
    int lane = threadIdx.x & 31;
    if (tok >= NTOK) return;
    const float* xr = x + (size_t)tok * DIM;
    float acc[NEXP];
#pragma unroll
    for (int e = 0; e < NEXP; e++) acc[e] = 0.f;
    for (int d = lane; d < DIM; d += 32) {
        float xv = xr[d];
        const float* wr = Wg + d * NEXP;
#pragma unroll
        for (int e = 0; e < NEXP; e++) acc[e] += xv * wr[e];
    }
#pragma unroll
    for (int off = 16; off; off >>= 1)
#pragma unroll
        for (int e = 0; e < NEXP; e++)
            acc[e] += __shfl_xor_sync(0xffffffffu, acc[e], off);
    if (lane == 0) {
        float logit[NEXP], m = -1e30f;
#pragma unroll
        for (int e = 0; e < NEXP; e++) { logit[e] = acc[e] + bg[e]; m = fmaxf(m, logit[e]); }
        float p[NEXP], s = 0.f;
#pragma unroll
        for (int e = 0; e < NEXP; e++) { p[e] = expf(logit[e] - m); s += p[e]; }
        float inv = 1.f / s;
#pragma unroll
        for (int e = 0; e < NEXP; e++) p[e] *= inv;
        int e0 = 0;
#pragma unroll
        for (int e = 1; e < NEXP; e++) if (p[e] > p[e0]) e0 = e;
        int e1 = (e0 == 0) ? 1 : 0;
#pragma unroll
        for (int e = 0; e < NEXP; e++) if (e != e0 && p[e] > p[e1]) e1 = e;
        g_wgt[2 * tok + 0] = p[e0];
        g_wgt[2 * tok + 1] = p[e1];
        int p0 = atomicAdd(&g_cnt[e0], 1); g_list[e0][p0] = 2 * tok + 0;
        int p1 = atomicAdd(&g_cnt[e1], 1); g_list[e1][p1] = 2 * tok + 1;
    }
}

// ---------------- HMMA fp16 2-term gathered GEMM ----------------
// C = A_fp16 * (B_hi + B_lo).  CTA 128x128, 256 thr, warps 4(m) x 2(n),
// K-chunk 64, 2-stage cp.async double buffer, 48KB/stage -> 2 CTAs/SM.
template <bool PHASE1>
__global__ void __launch_bounds__(256, 2)
moe_gemm(const float* __restrict__ bias, float* __restrict__ out) {
    constexpr int KD  = PHASE1 ? DIM : HID;
    constexpr int ND  = PHASE1 ? HID : DIM;
    constexpr int NCH = KD / 64;
    constexpr int STG = 48 * 1024;   // A 16KB | Bh 16KB | Bl 16KB

    const __half* A  = PHASE1 ? g_x    : g_h;
    const __half* Bh = PHASE1 ? g_w1_hi : g_w2_hi;
    const __half* Bl = PHASE1 ? g_w1_lo : g_w2_lo;

    const int e   = blockIdx.z;
    const int cnt = g_cnt[e];
    const int m0  = blockIdx.y * 128;
    if (m0 >= cnt) return;
    const int n0  = blockIdx.x * 128;
    const int tid = threadIdx.x;

    extern __shared__ char smraw[];
    char* tilep = (char*)(((uintptr_t)smraw + 1023) & ~(uintptr_t)1023);
    const uint32_t sbase = smem_u32(tilep);
    __shared__ float s_bias[128];
    if (tid < 128) s_bias[tid] = bias[(size_t)e * ND + n0 + tid];

    // ---- load mapping: thread covers 16B seg (tid&7) of rows (tid>>3)+32p ----
    const int seg = tid & 7;
    const int rg  = tid >> 3;
    uint32_t aoff[4], boff[4], avalid[4], swzo[4];
#pragma unroll
    for (int p = 0; p < 4; p++) {
        int r   = rg + 32 * p;
        int idx = m0 + r;
        int a   = (idx < cnt) ? g_list[e][idx] : 0;
        int ra  = PHASE1 ? (a >> 1) : a;
        avalid[p] = (idx < cnt) ? 16u : 0u;
        aoff[p]   = (uint32_t)ra * KD + seg * 8;
        boff[p]   = ((uint32_t)e * ND + n0 + r) * KD + seg * 8;
        swzo[p]   = SWZ(r * 128 + seg * 16);
    }

    // ---- fragment addressing ----
    const int lane = tid & 31;
    const int wid  = tid >> 5;
    const int wm   = wid >> 1;       // 0..3
    const int wn   = wid & 1;        // 0..1
    uint32_t abase[2], axor[2], bbase[4], bxor[4];
#pragma unroll
    for (int mf = 0; mf < 2; mf++) {
        int row   = wm * 32 + mf * 16 + (lane & 15);
        abase[mf] = row * 128 + (lane >> 4) * 16;
        axor[mf]  = (row & 7) << 4;
    }
#pragma unroll
    for (int p = 0; p < 4; p++) {
        int row  = wn * 64 + p * 16 + (lane & 15);
        bbase[p] = row * 128 + (lane >> 4) * 16;
        bxor[p]  = (row & 7) << 4;
    }

    float acc[2][8][4];
#pragma unroll
    for (int i = 0; i < 2; i++)
#pragma unroll
        for (int j = 0; j < 8; j++)
#pragma unroll
            for (int q = 0; q < 4; q++) acc[i][j][q] = 0.f;

#define ISSUE_CHUNK(CC, BUF) do {                                          \
        const uint32_t _ko = (uint32_t)(CC) * 64;                          \
        uint32_t _sb = sbase + (BUF) * STG;                                \
        _Pragma("unroll")                                                  \
        for (int p = 0; p < 4; p++) {                                      \
            cp16(_sb + swzo[p],         A  + aoff[p] + _ko, avalid[p]);    \
            cp16(_sb + 16384 + swzo[p], Bh + boff[p] + _ko, 16u);          \
            cp16(_sb + 32768 + swzo[p], Bl + boff[p] + _ko, 16u);          \
        }                                                                  \
        CP_COMMIT();                                                       \
    } while (0)

    // ---- prologue ----
    ISSUE_CHUNK(0, 0);

    for (int c = 0; c < NCH; ++c) {
        if (c + 1 < NCH) {
            ISSUE_CHUNK(c + 1, (c + 1) & 1);
            CP_WAIT(1);
        } else {
            CP_WAIT(0);
        }
        __syncthreads();

        const uint32_t sb = sbase + (c & 1) * STG;
#pragma unroll
        for (int kk = 0; kk < 4; kk++) {
            uint32_t ah[2][4], bh[4][4], bl[4][4];
#pragma unroll
            for (int mf = 0; mf < 2; mf++)
                ldsm4(ah[mf], sb + ((abase[mf] + kk * 32) ^ axor[mf]));
#pragma unroll
            for (int p = 0; p < 4; p++) {
                ldsm4(bh[p], sb + 16384 + ((bbase[p] + kk * 32) ^ bxor[p]));
                ldsm4(bl[p], sb + 32768 + ((bbase[p] + kk * 32) ^ bxor[p]));
            }
            // term 1: A * Bh
#pragma unroll
            for (int mf = 0; mf < 2; mf++)
#pragma unroll
                for (int p = 0; p < 4; p++) {
                    mma16816(acc[mf][2 * p],     ah[mf], bh[p][0], bh[p][2]);
                    mma16816(acc[mf][2 * p + 1], ah[mf], bh[p][1], bh[p][3]);
                }
            // term 2: A * Bl
#pragma unroll
            for (int mf = 0; mf < 2; mf++)
#pragma unroll
                for (int p = 0; p < 4; p++) {
                    mma16816(acc[mf][2 * p],     ah[mf], bl[p][0], bl[p][2]);
                    mma16816(acc[mf][2 * p + 1], ah[mf], bl[p][1], bl[p][3]);
                }
        }
        __syncthreads();
    }
#undef ISSUE_CHUNK

    // ---- epilogue ----
    const int quad  = lane >> 2;
    const int qid   = lane & 3;
    const int ncol0 = wn * 64;

#pragma unroll
    for (int mf = 0; mf < 2; mf++) {
#pragma unroll
        for (int rv = 0; rv < 2; rv++) {
            int midx = m0 + wm * 32 + mf * 16 + rv * 8 + quad;
            if (midx >= cnt) continue;
            int a = g_list[e][midx];
            if (PHASE1) {
                __half* dh = g_h + (size_t)a * HID + n0;
#pragma unroll
                for (int nf = 0; nf < 8; nf++) {
                    int nloc = ncol0 + nf * 8 + 2 * qid;
                    float v0 = fmaxf(acc[mf][nf][2 * rv]     + s_bias[nloc],     0.f);
                    float v1 = fmaxf(acc[mf][nf][2 * rv + 1] + s_bias[nloc + 1], 0.f);
                    *reinterpret_cast<uint32_t*>(dh + nloc) = pack_h2(v0, v1);
                }
            } else {
                float w = g_wgt[a];
                float* op = out + (size_t)(a >> 1) * DIM + n0;
#pragma unroll
                for (int nf = 0; nf < 8; nf++) {
                    int nloc = ncol0 + nf * 8 + 2 * qid;
                    atomicAdd(op + nloc,     (acc[mf][nf][2 * rv]     + s_bias[nloc])     * w);
                    atomicAdd(op + nloc + 1, (acc[mf][nf][2 * rv + 1] + s_bias[nloc + 1]) * w);
                }
            }
        }
    }
}

// ---------------- launch ----------------
extern "C" void kernel_launch(void* const* d_in, const int* in_sizes, int n_in,
                              void* d_out, int out_size) {
    const float* x  = (const float*)d_in[0];
    const float* Wg = (const float*)d_in[1];
    const float* bg = (const float*)d_in[2];
    const float* W1 = (const float*)d_in[3];
    const float* b1 = (const float*)d_in[4];
    const float* W2 = (const float*)d_in[5];
    const float* b2 = (const float*)d_in[6];
    float* out = (float*)d_out;

    const int SMEM_BYTES = 2 * 48 * 1024 + 1024;
    cudaFuncSetAttribute((const void*)moe_gemm<true>,
                         cudaFuncAttributeMaxDynamicSharedMemorySize, SMEM_BYTES);
    cudaFuncSetAttribute((const void*)moe_gemm<false>,
                         cudaFuncAttributeMaxDynamicSharedMemorySize, SMEM_BYTES);

    __half *w1h, *w1l, *w2h, *w2l;
    cudaGetSymbolAddress((void**)&w1h, g_w1_hi);
    cudaGetSymbolAddress((void**)&w1l, g_w1_lo);
    cudaGetSymbolAddress((void**)&w2h, g_w2_hi);
    cudaGetSymbolAddress((void**)&w2l, g_w2_lo);

    zero_kernel<<<(NTOK * DIM) / (256 * 4), 256>>>(out);
    conv_x<<<(NTOK * DIM) / (256 * 8), 256>>>(x);
    conv_w<<<dim3(HID / 32, DIM / 32, NEXP), dim3(16, 16)>>>(W1, w1h, w1l, DIM, HID);
    conv_w<<<dim3(DIM / 32, HID / 32, NEXP), dim3(16, 16)>>>(W2, w2h, w2l, HID, DIM);
    gating_kernel<<<(NTOK * 32) / 256, 256>>>(x, Wg, bg);

    moe_gemm<true><<<dim3(HID / 128, MAXA / 128, NEXP), 256, SMEM_BYTES>>>(b1, nullptr);
    moe_gemm<false><<<dim3(DIM / 128, MAXA / 128, NEXP), 256, SMEM_BYTES>>>(b2, out);
}

// round 7
// speedup vs baseline: 2.3979x; 1.4617x over previous
#include <cuda_runtime.h>
#include <cuda_fp16.h>
#include <cstdint>
#include <math.h>

#define NTOK 4096
#define DIM  1024
#define HID  4096
#define NEXP 8
#define MAXA (NTOK * 2)

// ---------------- device scratch (static, allocation-free) ----------------
__device__ int   g_cnt[NEXP];
__device__ int   g_list[NEXP][MAXA];
__device__ float g_wgt[MAXA];
__device__ __half g_x[(size_t)NTOK * DIM];
__device__ __half g_w1[(size_t)NEXP * HID * DIM];   // [e][h][d]
__device__ __half g_w2[(size_t)NEXP * DIM * HID];   // [e][d][h]
__device__ __half g_h[(size_t)MAXA * HID];

// ---------------- helpers ----------------
__device__ __forceinline__ uint32_t smem_u32(const void* p) {
    uint32_t a;
    asm("{ .reg .u64 t; cvta.to.shared.u64 t, %1; cvt.u32.u64 %0, t; }" : "=r"(a) : "l"(p));
    return a;
}
__device__ __forceinline__ void cp16(uint32_t dst, const void* src, uint32_t srcsz) {
    asm volatile("cp.async.cg.shared.global [%0], [%1], 16, %2;"
                 :: "r"(dst), "l"(src), "r"(srcsz) : "memory");
}
#define CP_COMMIT() asm volatile("cp.async.commit_group;" ::: "memory")
#define CP_WAIT(n)  asm volatile("cp.async.wait_group %0;" :: "n"(n) : "memory")

__device__ __forceinline__ void ldsm4(uint32_t* r, uint32_t addr) {
    asm volatile("ldmatrix.sync.aligned.m8n8.x4.shared.b16 {%0,%1,%2,%3}, [%4];"
                 : "=r"(r[0]), "=r"(r[1]), "=r"(r[2]), "=r"(r[3]) : "r"(addr));
}
__device__ __forceinline__ void mma16816(float* c, const uint32_t* a, uint32_t b0, uint32_t b1) {
    asm volatile(
        "mma.sync.aligned.m16n8k16.row.col.f32.f16.f16.f32 "
        "{%0,%1,%2,%3}, {%4,%5,%6,%7}, {%8,%9}, {%0,%1,%2,%3};"
        : "+f"(c[0]), "+f"(c[1]), "+f"(c[2]), "+f"(c[3])
        : "r"(a[0]), "r"(a[1]), "r"(a[2]), "r"(a[3]), "r"(b0), "r"(b1));
}
__device__ __forceinline__ uint32_t pack_h2(float a, float b) {
    __half2 t = __floats2half2_rn(a, b);
    return *reinterpret_cast<uint32_t*>(&t);
}
#define SWZ(o) ((o) ^ (((o) >> 3) & 0x70))

// ---------------- phase 0: zero out + counters ----------------
__global__ void zero_kernel(float* __restrict__ out) {
    size_t i = ((size_t)blockIdx.x * blockDim.x + threadIdx.x) * 4;
    if (i < (size_t)NTOK * DIM)
        *reinterpret_cast<float4*>(out + i) = make_float4(0.f, 0.f, 0.f, 0.f);
    if (blockIdx.x == 0 && threadIdx.x < NEXP) g_cnt[threadIdx.x] = 0;
}

// ---------------- convert x -> fp16 ----------------
__global__ void conv_x(const float* __restrict__ x) {
    size_t i = ((size_t)blockIdx.x * blockDim.x + threadIdx.x) * 8;
    float v[8];
    *reinterpret_cast<float4*>(v)     = *reinterpret_cast<const float4*>(x + i);
    *reinterpret_cast<float4*>(v + 4) = *reinterpret_cast<const float4*>(x + i + 4);
    uint32_t p[4];
#pragma unroll
    for (int j = 0; j < 4; j++) p[j] = pack_h2(v[2 * j], v[2 * j + 1]);
    *reinterpret_cast<uint4*>(g_x + i) = make_uint4(p[0], p[1], p[2], p[3]);
}

// ------- transpose-convert W [e][R][C] -> [e][C][R] fp16 (packed stores) -------
__global__ void conv_w(const float* __restrict__ src, __half* __restrict__ dh,
                       int R, int C) {
    __shared__ float t[32][33];
    int e  = blockIdx.z;
    int r0 = blockIdx.y * 32, c0 = blockIdx.x * 32;
    int tx = threadIdx.x;   // 0..15
    int ty = threadIdx.y;   // 0..15
    const float* sp = src + (size_t)e * R * C;
#pragma unroll
    for (int j = 0; j < 2; j++) {
        int r = ty + 16 * j;
        float2 v = *reinterpret_cast<const float2*>(sp + (size_t)(r0 + r) * C + c0 + 2 * tx);
        t[r][2 * tx]     = v.x;
        t[r][2 * tx + 1] = v.y;
    }
    __syncthreads();
#pragma unroll
    for (int j = 0; j < 2; j++) {
        int cc = ty + 16 * j;
        float v0 = t[2 * tx][cc], v1 = t[2 * tx + 1][cc];
        size_t o = ((size_t)e * C + c0 + cc) * R + r0 + 2 * tx;
        *reinterpret_cast<uint32_t*>(dh + o) = pack_h2(v0, v1);
    }
}

// ---------------- gating (1 warp / token) ----------------
__global__ void gating_kernel(const float* __restrict__ x,
                              const float* __restrict__ Wg,
                              const float* __restrict__ bg) {
    int tok  = (blockIdx.x * blockDim.x + threadIdx.x) >> 5;
    int lane = threadIdx.x & 31;
    if (tok >= NTOK) return;
    const float* xr = x + (size_t)tok * DIM;
    float acc[NEXP];
#pragma unroll
    for (int e = 0; e < NEXP; e++) acc[e] = 0.f;
    for (int d = lane; d < DIM; d += 32) {
        float xv = xr[d];
        const float* wr = Wg + d * NEXP;
#pragma unroll
        for (int e = 0; e < NEXP; e++) acc[e] += xv * wr[e];
    }
#pragma unroll
    for (int off = 16; off; off >>= 1)
#pragma unroll
        for (int e = 0; e < NEXP; e++)
            acc[e] += __shfl_xor_sync(0xffffffffu, acc[e], off);
    if (lane == 0) {
        float logit[NEXP], m = -1e30f;
#pragma unroll
        for (int e = 0; e < NEXP; e++) { logit[e] = acc[e] + bg[e]; m = fmaxf(m, logit[e]); }
        float p[NEXP], s = 0.f;
#pragma unroll
        for (int e = 0; e < NEXP; e++) { p[e] = expf(logit[e] - m); s += p[e]; }
        float inv = 1.f / s;
#pragma unroll
        for (int e = 0; e < NEXP; e++) p[e] *= inv;
        int e0 = 0;
#pragma unroll
        for (int e = 1; e < NEXP; e++) if (p[e] > p[e0]) e0 = e;
        int e1 = (e0 == 0) ? 1 : 0;
#pragma unroll
        for (int e = 0; e < NEXP; e++) if (e != e0 && p[e] > p[e1]) e1 = e;
        g_wgt[2 * tok + 0] = p[e0];
        g_wgt[2 * tok + 1] = p[e1];
        int p0 = atomicAdd(&g_cnt[e0], 1); g_list[e0][p0] = 2 * tok + 0;
        int p1 = atomicAdd(&g_cnt[e1], 1); g_list[e1][p1] = 2 * tok + 1;
    }
}

// ---------------- HMMA fp16 gathered GEMM ----------------
// C = A_fp16 * B_fp16 (fp32 accum). CTA 128x128, 256 thr, warps 4(m) x 2(n),
// K-chunk 128 (two 64-k sub-buffers), 2-stage cp.async, 64KB/stage -> 2 CTAs/SM.
// Stage layout: [A0 16K][A1 16K][B0 16K][B1 16K]  (sub-buffer = 64 k-elems)
template <bool PHASE1>
__global__ void __launch_bounds__(256, 2)
moe_gemm(const float* __restrict__ bias, float* __restrict__ out) {
    constexpr int KD  = PHASE1 ? DIM : HID;
    constexpr int ND  = PHASE1 ? HID : DIM;
    constexpr int NCH = KD / 128;
    constexpr int STG = 64 * 1024;

    const __half* A = PHASE1 ? g_x  : g_h;
    const __half* B = PHASE1 ? g_w1 : g_w2;

    const int e   = blockIdx.z;
    const int cnt = g_cnt[e];
    const int m0  = blockIdx.y * 128;
    if (m0 >= cnt) return;
    const int n0  = blockIdx.x * 128;
    const int tid = threadIdx.x;

    extern __shared__ char smraw[];
    char* tilep = (char*)(((uintptr_t)smraw + 1023) & ~(uintptr_t)1023);
    const uint32_t sbase = smem_u32(tilep);
    __shared__ float s_bias[128];
    if (tid < 128) s_bias[tid] = bias[(size_t)e * ND + n0 + tid];

    // ---- load mapping: thread covers 16B seg (tid&7) of rows (tid>>3)+32p ----
    const int seg = tid & 7;
    const int rg  = tid >> 3;
    uint32_t aoff[4], boff[4], avalid[4], swzo[4];
#pragma unroll
    for (int p = 0; p < 4; p++) {
        int r   = rg + 32 * p;
        int idx = m0 + r;
        int a   = (idx < cnt) ? g_list[e][idx] : 0;
        int ra  = PHASE1 ? (a >> 1) : a;
        avalid[p] = (idx < cnt) ? 16u : 0u;
        aoff[p]   = (uint32_t)ra * KD + seg * 8;
        boff[p]   = ((uint32_t)e * ND + n0 + r) * KD + seg * 8;
        swzo[p]   = SWZ(r * 128 + seg * 16);
    }

    // ---- fragment addressing ----
    const int lane = tid & 31;
    const int wid  = tid >> 5;
    const int wm   = wid >> 1;       // 0..3
    const int wn   = wid & 1;        // 0..1
    uint32_t abase[2], axor[2], bbase[4], bxor[4];
#pragma unroll
    for (int mf = 0; mf < 2; mf++) {
        int row   = wm * 32 + mf * 16 + (lane & 15);
        abase[mf] = row * 128 + (lane >> 4) * 16;
        axor[mf]  = (row & 7) << 4;
    }
#pragma unroll
    for (int p = 0; p < 4; p++) {
        int row  = wn * 64 + p * 16 + (lane & 15);
        bbase[p] = row * 128 + (lane >> 4) * 16;
        bxor[p]  = (row & 7) << 4;
    }

    float acc[2][8][4];
#pragma unroll
    for (int i = 0; i < 2; i++)
#pragma unroll
        for (int j = 0; j < 8; j++)
#pragma unroll
            for (int q = 0; q < 4; q++) acc[i][j][q] = 0.f;

#define ISSUE_CHUNK(CC, BUF) do {                                              \
        const uint32_t _ko = (uint32_t)(CC) * 128;                             \
        uint32_t _sb = sbase + (BUF) * STG;                                    \
        _Pragma("unroll")                                                      \
        for (int s = 0; s < 2; s++) {                                          \
            _Pragma("unroll")                                                  \
            for (int p = 0; p < 4; p++) {                                      \
                cp16(_sb + s * 16384 + swzo[p],                                \
                     A + aoff[p] + _ko + s * 64, avalid[p]);                   \
                cp16(_sb + 32768 + s * 16384 + swzo[p],                        \
                     B + boff[p] + _ko + s * 64, 16u);                         \
            }                                                                  \
        }                                                                      \
        CP_COMMIT();                                                           \
    } while (0)

    // ---- prologue ----
    ISSUE_CHUNK(0, 0);

    for (int c = 0; c < NCH; ++c) {
        if (c + 1 < NCH) {
            ISSUE_CHUNK(c + 1, (c + 1) & 1);
            CP_WAIT(1);
        } else {
            CP_WAIT(0);
        }
        __syncthreads();

        const uint32_t sb = sbase + (c & 1) * STG;
#pragma unroll
        for (int kk = 0; kk < 8; kk++) {
            const uint32_t sub = (kk >> 2) * 16384;
            const uint32_t k4  = (kk & 3) * 32;
            uint32_t ah[2][4], bb[4][4];
#pragma unroll
            for (int mf = 0; mf < 2; mf++)
                ldsm4(ah[mf], sb + sub + ((abase[mf] + k4) ^ axor[mf]));
#pragma unroll
            for (int p = 0; p < 4; p++)
                ldsm4(bb[p], sb + 32768 + sub + ((bbase[p] + k4) ^ bxor[p]));
#pragma unroll
            for (int mf = 0; mf < 2; mf++)
#pragma unroll
                for (int p = 0; p < 4; p++) {
                    mma16816(acc[mf][2 * p],     ah[mf], bb[p][0], bb[p][2]);
                    mma16816(acc[mf][2 * p + 1], ah[mf], bb[p][1], bb[p][3]);
                }
        }
        __syncthreads();
    }
#undef ISSUE_CHUNK

    // ---- epilogue ----
    const int quad  = lane >> 2;
    const int qid   = lane & 3;
    const int ncol0 = wn * 64;

#pragma unroll
    for (int mf = 0; mf < 2; mf++) {
#pragma unroll
        for (int rv = 0; rv < 2; rv++) {
            int midx = m0 + wm * 32 + mf * 16 + rv * 8 + quad;
            if (midx >= cnt) continue;
            int a = g_list[e][midx];
            if (PHASE1) {
                __half* dh = g_h + (size_t)a * HID + n0;
#pragma unroll
                for (int nf = 0; nf < 8; nf++) {
                    int nloc = ncol0 + nf * 8 + 2 * qid;
                    float v0 = fmaxf(acc[mf][nf][2 * rv]     + s_bias[nloc],     0.f);
                    float v1 = fmaxf(acc[mf][nf][2 * rv + 1] + s_bias[nloc + 1], 0.f);
                    *reinterpret_cast<uint32_t*>(dh + nloc) = pack_h2(v0, v1);
                }
            } else {
                float w = g_wgt[a];
                float* op = out + (size_t)(a >> 1) * DIM + n0;
#pragma unroll
                for (int nf = 0; nf < 8; nf++) {
                    int nloc = ncol0 + nf * 8 + 2 * qid;
                    atomicAdd(op + nloc,     (acc[mf][nf][2 * rv]     + s_bias[nloc])     * w);
                    atomicAdd(op + nloc + 1, (acc[mf][nf][2 * rv + 1] + s_bias[nloc + 1]) * w);
                }
            }
        }
    }
}

// ---------------- launch ----------------
extern "C" void kernel_launch(void* const* d_in, const int* in_sizes, int n_in,
                              void* d_out, int out_size) {
    const float* x  = (const float*)d_in[0];
    const float* Wg = (const float*)d_in[1];
    const float* bg = (const float*)d_in[2];
    const float* W1 = (const float*)d_in[3];
    const float* b1 = (const float*)d_in[4];
    const float* W2 = (const float*)d_in[5];
    const float* b2 = (const float*)d_in[6];
    float* out = (float*)d_out;

    const int SMEM_BYTES = 2 * 64 * 1024 + 1024;
    cudaFuncSetAttribute((const void*)moe_gemm<true>,
                         cudaFuncAttributeMaxDynamicSharedMemorySize, SMEM_BYTES);
    cudaFuncSetAttribute((const void*)moe_gemm<false>,
                         cudaFuncAttributeMaxDynamicSharedMemorySize, SMEM_BYTES);

    __half *w1p, *w2p;
    cudaGetSymbolAddress((void**)&w1p, g_w1);
    cudaGetSymbolAddress((void**)&w2p, g_w2);

    zero_kernel<<<(NTOK * DIM) / (256 * 4), 256>>>(out);
    conv_x<<<(NTOK * DIM) / (256 * 8), 256>>>(x);
    conv_w<<<dim3(HID / 32, DIM / 32, NEXP), dim3(16, 16)>>>(W1, w1p, DIM, HID);
    conv_w<<<dim3(DIM / 32, HID / 32, NEXP), dim3(16, 16)>>>(W2, w2p, HID, DIM);
    gating_kernel<<<(NTOK * 32) / 256, 256>>>(x, Wg, bg);

    moe_gemm<true><<<dim3(HID / 128, MAXA / 128, NEXP), 256, SMEM_BYTES>>>(b1, nullptr);
    moe_gemm<false><<<dim3(DIM / 128, MAXA / 128, NEXP), 256, SMEM_BYTES>>>(b2, out);
}

// round 8
// speedup vs baseline: 2.4495x; 1.0215x over previous
#include <cuda_runtime.h>
#include <cuda_fp16.h>
#include <cstdint>
#include <math.h>

#define NTOK 4096
#define DIM  1024
#define HID  4096
#define NEXP 8
#define MAXA (NTOK * 2)

// ---------------- device scratch (static, allocation-free) ----------------
__device__ int   g_cnt[NEXP];
__device__ int   g_list[NEXP][MAXA];
__device__ float g_wgt[MAXA];
__device__ __half g_x[(size_t)NTOK * DIM];
__device__ __half g_w1[(size_t)NEXP * HID * DIM];   // [e][h][d]
__device__ __half g_w2[(size_t)NEXP * DIM * HID];   // [e][d][h]
__device__ __half g_h[(size_t)MAXA * HID];

// ---------------- helpers ----------------
__device__ __forceinline__ uint32_t smem_u32(const void* p) {
    uint32_t a;
    asm("{ .reg .u64 t; cvta.to.shared.u64 t, %1; cvt.u32.u64 %0, t; }" : "=r"(a) : "l"(p));
    return a;
}
__device__ __forceinline__ void cp16(uint32_t dst, const void* src, uint32_t srcsz) {
    asm volatile("cp.async.cg.shared.global [%0], [%1], 16, %2;"
                 :: "r"(dst), "l"(src), "r"(srcsz) : "memory");
}
#define CP_COMMIT() asm volatile("cp.async.commit_group;" ::: "memory")
#define CP_WAIT(n)  asm volatile("cp.async.wait_group %0;" :: "n"(n) : "memory")

__device__ __forceinline__ void ldsm4(uint32_t* r, uint32_t addr) {
    asm volatile("ldmatrix.sync.aligned.m8n8.x4.shared.b16 {%0,%1,%2,%3}, [%4];"
                 : "=r"(r[0]), "=r"(r[1]), "=r"(r[2]), "=r"(r[3]) : "r"(addr));
}
__device__ __forceinline__ void mma16816(float* c, const uint32_t* a, uint32_t b0, uint32_t b1) {
    asm volatile(
        "mma.sync.aligned.m16n8k16.row.col.f32.f16.f16.f32 "
        "{%0,%1,%2,%3}, {%4,%5,%6,%7}, {%8,%9}, {%0,%1,%2,%3};"
        : "+f"(c[0]), "+f"(c[1]), "+f"(c[2]), "+f"(c[3])
        : "r"(a[0]), "r"(a[1]), "r"(a[2]), "r"(a[3]), "r"(b0), "r"(b1));
}
__device__ __forceinline__ void mma16816_1(float* c, uint32_t a0, uint32_t a1,
                                           uint32_t a2, uint32_t a3,
                                           uint32_t b0, uint32_t b1) {
    asm volatile(
        "mma.sync.aligned.m16n8k16.row.col.f32.f16.f16.f32 "
        "{%0,%1,%2,%3}, {%4,%5,%6,%7}, {%8,%9}, {%0,%1,%2,%3};"
        : "+f"(c[0]), "+f"(c[1]), "+f"(c[2]), "+f"(c[3])
        : "r"(a0), "r"(a1), "r"(a2), "r"(a3), "r"(b0), "r"(b1));
}
__device__ __forceinline__ uint32_t pack_h2(float a, float b) {
    __half2 t = __floats2half2_rn(a, b);
    return *reinterpret_cast<uint32_t*>(&t);
}
#define SWZ(o) ((o) ^ (((o) >> 3) & 0x70))

// ---------------- phase 0: zero out + counters ----------------
__global__ void zero_kernel(float* __restrict__ out) {
    size_t i = ((size_t)blockIdx.x * blockDim.x + threadIdx.x) * 4;
    if (i < (size_t)NTOK * DIM)
        *reinterpret_cast<float4*>(out + i) = make_float4(0.f, 0.f, 0.f, 0.f);
    if (blockIdx.x == 0 && threadIdx.x < NEXP) g_cnt[threadIdx.x] = 0;
}

// ---------------- convert x -> fp16 ----------------
__global__ void conv_x(const float* __restrict__ x) {
    size_t i = ((size_t)blockIdx.x * blockDim.x + threadIdx.x) * 8;
    float v[8];
    *reinterpret_cast<float4*>(v)     = *reinterpret_cast<const float4*>(x + i);
    *reinterpret_cast<float4*>(v + 4) = *reinterpret_cast<const float4*>(x + i + 4);
    uint32_t p[4];
#pragma unroll
    for (int j = 0; j < 4; j++) p[j] = pack_h2(v[2 * j], v[2 * j + 1]);
    *reinterpret_cast<uint4*>(g_x + i) = make_uint4(p[0], p[1], p[2], p[3]);
}

// ------- transpose-convert W [e][R][C] -> [e][C][R] fp16; 32(R) x 64(C) tiles -------
__global__ void conv_w(const float* __restrict__ src, __half* __restrict__ dh,
                       int R, int C) {
    __shared__ float t[32][65];
    int e  = blockIdx.z;
    int r0 = blockIdx.y * 32, c0 = blockIdx.x * 64;
    int tx = threadIdx.x;   // 0..15
    int ty = threadIdx.y;   // 0..15
    const float* sp = src + (size_t)e * R * C;
#pragma unroll
    for (int j = 0; j < 2; j++) {
        int r = ty + 16 * j;
        float4 v = *reinterpret_cast<const float4*>(sp + (size_t)(r0 + r) * C + c0 + 4 * tx);
        t[r][4 * tx + 0] = v.x;
        t[r][4 * tx + 1] = v.y;
        t[r][4 * tx + 2] = v.z;
        t[r][4 * tx + 3] = v.w;
    }
    __syncthreads();
#pragma unroll
    for (int j = 0; j < 4; j++) {
        int cc = ty + 16 * j;
        float v0 = t[2 * tx][cc], v1 = t[2 * tx + 1][cc];
        size_t o = ((size_t)e * C + c0 + cc) * R + r0 + 2 * tx;
        *reinterpret_cast<uint32_t*>(dh + o) = pack_h2(v0, v1);
    }
}

// ---------------- gating (1 warp / token) ----------------
__global__ void gating_kernel(const float* __restrict__ x,
                              const float* __restrict__ Wg,
                              const float* __restrict__ bg) {
    int tok  = (blockIdx.x * blockDim.x + threadIdx.x) >> 5;
    int lane = threadIdx.x & 31;
    if (tok >= NTOK) return;
    const float* xr = x + (size_t)tok * DIM;
    float acc[NEXP];
#pragma unroll
    for (int e = 0; e < NEXP; e++) acc[e] = 0.f;
    for (int d = lane; d < DIM; d += 32) {
        float xv = xr[d];
        const float* wr = Wg + d * NEXP;
#pragma unroll
        for (int e = 0; e < NEXP; e++) acc[e] += xv * wr[e];
    }
#pragma unroll
    for (int off = 16; off; off >>= 1)
#pragma unroll
        for (int e = 0; e < NEXP; e++)
            acc[e] += __shfl_xor_sync(0xffffffffu, acc[e], off);
    if (lane == 0) {
        float logit[NEXP], m = -1e30f;
#pragma unroll
        for (int e = 0; e < NEXP; e++) { logit[e] = acc[e] + bg[e]; m = fmaxf(m, logit[e]); }
        float p[NEXP], s = 0.f;
#pragma unroll
        for (int e = 0; e < NEXP; e++) { p[e] = expf(logit[e] - m); s += p[e]; }
        float inv = 1.f / s;
#pragma unroll
        for (int e = 0; e < NEXP; e++) p[e] *= inv;
        int e0 = 0;
#pragma unroll
        for (int e = 1; e < NEXP; e++) if (p[e] > p[e0]) e0 = e;
        int e1 = (e0 == 0) ? 1 : 0;
#pragma unroll
        for (int e = 0; e < NEXP; e++) if (e != e0 && p[e] > p[e1]) e1 = e;
        g_wgt[2 * tok + 0] = p[e0];
        g_wgt[2 * tok + 1] = p[e1];
        int p0 = atomicAdd(&g_cnt[e0], 1); g_list[e0][p0] = 2 * tok + 0;
        int p1 = atomicAdd(&g_cnt[e1], 1); g_list[e1][p1] = 2 * tok + 1;
    }
}

// ---------------- phase1: 128x128 CTA, warps 4m x 2n ----------------
__global__ void __launch_bounds__(256, 2)
moe_gemm1(const float* __restrict__ bias) {
    constexpr int KD  = DIM;
    constexpr int ND  = HID;
    constexpr int NCH = KD / 128;
    constexpr int STG = 64 * 1024;

    const __half* A = g_x;
    const __half* B = g_w1;

    const int e   = blockIdx.z;
    const int cnt = g_cnt[e];
    const int m0  = blockIdx.y * 128;
    if (m0 >= cnt) return;
    const int n0  = blockIdx.x * 128;
    const int tid = threadIdx.x;

    extern __shared__ char smraw[];
    char* tilep = (char*)(((uintptr_t)smraw + 1023) & ~(uintptr_t)1023);
    const uint32_t sbase = smem_u32(tilep);
    __shared__ float s_bias[128];
    if (tid < 128) s_bias[tid] = bias[(size_t)e * ND + n0 + tid];

    const int seg = tid & 7;
    const int rg  = tid >> 3;
    uint32_t aoff[4], boff[4], avalid[4], swzo[4];
#pragma unroll
    for (int p = 0; p < 4; p++) {
        int r   = rg + 32 * p;
        int idx = m0 + r;
        int a   = (idx < cnt) ? g_list[e][idx] : 0;
        avalid[p] = (idx < cnt) ? 16u : 0u;
        aoff[p]   = (uint32_t)(a >> 1) * KD + seg * 8;
        boff[p]   = ((uint32_t)e * ND + n0 + r) * KD + seg * 8;
        swzo[p]   = SWZ(r * 128 + seg * 16);
    }

    const int lane = tid & 31;
    const int wid  = tid >> 5;
    const int wm   = wid >> 1;
    const int wn   = wid & 1;
    uint32_t abase[2], axor[2], bbase[4], bxor[4];
#pragma unroll
    for (int mf = 0; mf < 2; mf++) {
        int row   = wm * 32 + mf * 16 + (lane & 15);
        abase[mf] = row * 128 + (lane >> 4) * 16;
        axor[mf]  = (row & 7) << 4;
    }
#pragma unroll
    for (int p = 0; p < 4; p++) {
        int row  = wn * 64 + p * 16 + (lane & 15);
        bbase[p] = row * 128 + (lane >> 4) * 16;
        bxor[p]  = (row & 7) << 4;
    }

    float acc[2][8][4];
#pragma unroll
    for (int i = 0; i < 2; i++)
#pragma unroll
        for (int j = 0; j < 8; j++)
#pragma unroll
            for (int q = 0; q < 4; q++) acc[i][j][q] = 0.f;

#define ISSUE_CHUNK1(CC, BUF) do {                                             \
        const uint32_t _ko = (uint32_t)(CC) * 128;                             \
        uint32_t _sb = sbase + (BUF) * STG;                                    \
        _Pragma("unroll")                                                      \
        for (int s = 0; s < 2; s++) {                                          \
            _Pragma("unroll")                                                  \
            for (int p = 0; p < 4; p++) {                                      \
                cp16(_sb + s * 16384 + swzo[p],                                \
                     A + aoff[p] + _ko + s * 64, avalid[p]);                   \
                cp16(_sb + 32768 + s * 16384 + swzo[p],                        \
                     B + boff[p] + _ko + s * 64, 16u);                         \
            }                                                                  \
        }                                                                      \
        CP_COMMIT();                                                           \
    } while (0)

    ISSUE_CHUNK1(0, 0);

    for (int c = 0; c < NCH; ++c) {
        if (c + 1 < NCH) {
            ISSUE_CHUNK1(c + 1, (c + 1) & 1);
            CP_WAIT(1);
        } else {
            CP_WAIT(0);
        }
        __syncthreads();

        const uint32_t sb = sbase + (c & 1) * STG;
#pragma unroll
        for (int kk = 0; kk < 8; kk++) {
            const uint32_t sub = (kk >> 2) * 16384;
            const uint32_t k4  = (kk & 3) * 32;
            uint32_t ah[2][4], bb[4][4];
#pragma unroll
            for (int mf = 0; mf < 2; mf++)
                ldsm4(ah[mf], sb + sub + ((abase[mf] + k4) ^ axor[mf]));
#pragma unroll
            for (int p = 0; p < 4; p++)
                ldsm4(bb[p], sb + 32768 + sub + ((bbase[p] + k4) ^ bxor[p]));
#pragma unroll
            for (int mf = 0; mf < 2; mf++)
#pragma unroll
                for (int p = 0; p < 4; p++) {
                    mma16816(acc[mf][2 * p],     ah[mf], bb[p][0], bb[p][2]);
                    mma16816(acc[mf][2 * p + 1], ah[mf], bb[p][1], bb[p][3]);
                }
        }
        __syncthreads();
    }
#undef ISSUE_CHUNK1

    const int quad  = lane >> 2;
    const int qid   = lane & 3;
    const int ncol0 = wn * 64;

#pragma unroll
    for (int mf = 0; mf < 2; mf++) {
#pragma unroll
        for (int rv = 0; rv < 2; rv++) {
            int midx = m0 + wm * 32 + mf * 16 + rv * 8 + quad;
            if (midx >= cnt) continue;
            int a = g_list[e][midx];
            __half* dh = g_h + (size_t)a * HID + n0;
#pragma unroll
            for (int nf = 0; nf < 8; nf++) {
                int nloc = ncol0 + nf * 8 + 2 * qid;
                float v0 = fmaxf(acc[mf][nf][2 * rv]     + s_bias[nloc],     0.f);
                float v1 = fmaxf(acc[mf][nf][2 * rv + 1] + s_bias[nloc + 1], 0.f);
                *reinterpret_cast<uint32_t*>(dh + nloc) = pack_h2(v0, v1);
            }
        }
    }
}

// ---------------- phase2: 64x64 CTA, warps 4m x 2n (warp tile 16x32) ----------------
// More CTAs (2048 active) -> ~7 full waves, kills the 1.73-wave quantization.
__global__ void __launch_bounds__(256, 2)
moe_gemm2(const float* __restrict__ bias, float* __restrict__ out) {
    constexpr int KD  = HID;
    constexpr int ND  = DIM;
    constexpr int NCH = KD / 128;
    constexpr int STG = 32 * 1024;   // [A0 8K][A1 8K][B0 8K][B1 8K]

    const __half* A = g_h;
    const __half* B = g_w2;

    const int e   = blockIdx.z;
    const int cnt = g_cnt[e];
    const int m0  = blockIdx.y * 64;
    if (m0 >= cnt) return;
    const int n0  = blockIdx.x * 64;
    const int tid = threadIdx.x;

    extern __shared__ char smraw[];
    char* tilep = (char*)(((uintptr_t)smraw + 1023) & ~(uintptr_t)1023);
    const uint32_t sbase = smem_u32(tilep);
    __shared__ float s_bias[64];
    if (tid < 64) s_bias[tid] = bias[(size_t)e * ND + n0 + tid];

    const int seg = tid & 7;
    const int rg  = tid >> 3;
    uint32_t aoff[2], boff[2], avalid[2], swzo[2];
#pragma unroll
    for (int p = 0; p < 2; p++) {
        int r   = rg + 32 * p;
        int idx = m0 + r;
        int a   = (idx < cnt) ? g_list[e][idx] : 0;
        avalid[p] = (idx < cnt) ? 16u : 0u;
        aoff[p]   = (uint32_t)a * KD + seg * 8;
        boff[p]   = ((uint32_t)e * ND + n0 + r) * KD + seg * 8;
        swzo[p]   = SWZ(r * 128 + seg * 16);
    }

    const int lane = tid & 31;
    const int wid  = tid >> 5;
    const int wm   = wid >> 1;       // 0..3, m offset wm*16
    const int wn   = wid & 1;        // 0..1, n offset wn*32
    uint32_t abase, axor, bbase[2], bxor[2];
    {
        int row = wm * 16 + (lane & 15);
        abase   = row * 128 + (lane >> 4) * 16;
        axor    = (row & 7) << 4;
    }
#pragma unroll
    for (int p = 0; p < 2; p++) {
        int row  = wn * 32 + p * 16 + (lane & 15);
        bbase[p] = row * 128 + (lane >> 4) * 16;
        bxor[p]  = (row & 7) << 4;
    }

    float acc[4][4];
#pragma unroll
    for (int j = 0; j < 4; j++)
#pragma unroll
        for (int q = 0; q < 4; q++) acc[j][q] = 0.f;

#define ISSUE_CHUNK2(CC, BUF) do {                                             \
        const uint32_t _ko = (uint32_t)(CC) * 128;                             \
        uint32_t _sb = sbase + (BUF) * STG;                                    \
        _Pragma("unroll")                                                      \
        for (int s = 0; s < 2; s++) {                                          \
            _Pragma("unroll")                                                  \
            for (int p = 0; p < 2; p++) {                                      \
                cp16(_sb + s * 8192 + swzo[p],                                 \
                     A + aoff[p] + _ko + s * 64, avalid[p]);                   \
                cp16(_sb + 16384 + s * 8192 + swzo[p],                         \
                     B + boff[p] + _ko + s * 64, 16u);                         \
            }                                                                  \
        }                                                                      \
        CP_COMMIT();                                                           \
    } while (0)

    ISSUE_CHUNK2(0, 0);

    for (int c = 0; c < NCH; ++c) {
        if (c + 1 < NCH) {
            ISSUE_CHUNK2(c + 1, (c + 1) & 1);
            CP_WAIT(1);
        } else {
            CP_WAIT(0);
        }
        __syncthreads();

        const uint32_t sb = sbase + (c & 1) * STG;
#pragma unroll
        for (int kk = 0; kk < 8; kk++) {
            const uint32_t sub = (kk >> 2) * 8192;
            const uint32_t k4  = (kk & 3) * 32;
            uint32_t ah[4], bb[2][4];
            ldsm4(ah, sb + sub + ((abase + k4) ^ axor));
#pragma unroll
            for (int p = 0; p < 2; p++)
                ldsm4(bb[p], sb + 16384 + sub + ((bbase[p] + k4) ^ bxor[p]));
#pragma unroll
            for (int p = 0; p < 2; p++) {
                mma16816_1(acc[2 * p],     ah[0], ah[1], ah[2], ah[3], bb[p][0], bb[p][2]);
                mma16816_1(acc[2 * p + 1], ah[0], ah[1], ah[2], ah[3], bb[p][1], bb[p][3]);
            }
        }
        __syncthreads();
    }
#undef ISSUE_CHUNK2

    const int quad  = lane >> 2;
    const int qid   = lane & 3;
    const int ncol0 = wn * 32;

#pragma unroll
    for (int rv = 0; rv < 2; rv++) {
        int midx = m0 + wm * 16 + rv * 8 + quad;
        if (midx >= cnt) continue;
        int a = g_list[e][midx];
        float w = g_wgt[a];
        float* op = out + (size_t)(a >> 1) * DIM + n0;
#pragma unroll
        for (int nf = 0; nf < 4; nf++) {
            int nloc = ncol0 + nf * 8 + 2 * qid;
            atomicAdd(op + nloc,     (acc[nf][2 * rv]     + s_bias[nloc])     * w);
            atomicAdd(op + nloc + 1, (acc[nf][2 * rv + 1] + s_bias[nloc + 1]) * w);
        }
    }
}

// ---------------- launch ----------------
extern "C" void kernel_launch(void* const* d_in, const int* in_sizes, int n_in,
                              void* d_out, int out_size) {
    const float* x  = (const float*)d_in[0];
    const float* Wg = (const float*)d_in[1];
    const float* bg = (const float*)d_in[2];
    const float* W1 = (const float*)d_in[3];
    const float* b1 = (const float*)d_in[4];
    const float* W2 = (const float*)d_in[5];
    const float* b2 = (const float*)d_in[6];
    float* out = (float*)d_out;

    const int SMEM1 = 2 * 64 * 1024 + 1024;
    const int SMEM2 = 2 * 32 * 1024 + 1024;
    cudaFuncSetAttribute((const void*)moe_gemm1,
                         cudaFuncAttributeMaxDynamicSharedMemorySize, SMEM1);
    cudaFuncSetAttribute((const void*)moe_gemm2,
                         cudaFuncAttributeMaxDynamicSharedMemorySize, SMEM2);

    __half *w1p, *w2p;
    cudaGetSymbolAddress((void**)&w1p, g_w1);
    cudaGetSymbolAddress((void**)&w2p, g_w2);

    zero_kernel<<<(NTOK * DIM) / (256 * 4), 256>>>(out);
    conv_x<<<(NTOK * DIM) / (256 * 8), 256>>>(x);
    conv_w<<<dim3(HID / 64, DIM / 32, NEXP), dim3(16, 16)>>>(W1, w1p, DIM, HID);
    conv_w<<<dim3(DIM / 64, HID / 32, NEXP), dim3(16, 16)>>>(W2, w2p, HID, DIM);
    gating_kernel<<<(NTOK * 32) / 256, 256>>>(x, Wg, bg);

    moe_gemm1<<<dim3(HID / 128, MAXA / 128, NEXP), 256, SMEM1>>>(b1);
    moe_gemm2<<<dim3(DIM / 64, MAXA / 64, NEXP), 256, SMEM2>>>(b2, out);
}

// round 10
// speedup vs baseline: 2.5184x; 1.0281x over previous
#include <cuda_runtime.h>
#include <cuda_fp16.h>
#include <cstdint>
#include <math.h>

#define NTOK 4096
#define DIM  1024
#define HID  4096
#define NEXP 8
#define MAXA (NTOK * 2)

// ---------------- device scratch (static, allocation-free) ----------------
__device__ int   g_cnt[NEXP];
__device__ int   g_list[NEXP][MAXA];
__device__ float g_wgt[MAXA];
__device__ __half g_x[(size_t)NTOK * DIM];
__device__ __half g_w1[(size_t)NEXP * DIM * HID];   // native [e][d][h]  (K-major rows of N)
__device__ __half g_w2[(size_t)NEXP * HID * DIM];   // native [e][h][d]
__device__ __half g_h[(size_t)MAXA * HID];

// ---------------- helpers ----------------
__device__ __forceinline__ uint32_t smem_u32(const void* p) {
    uint32_t a;
    asm("{ .reg .u64 t; cvta.to.shared.u64 t, %1; cvt.u32.u64 %0, t; }" : "=r"(a) : "l"(p));
    return a;
}
__device__ __forceinline__ void cp16(uint32_t dst, const void* src, uint32_t srcsz) {
    asm volatile("cp.async.cg.shared.global [%0], [%1], 16, %2;"
                 :: "r"(dst), "l"(src), "r"(srcsz) : "memory");
}
#define CP_COMMIT() asm volatile("cp.async.commit_group;" ::: "memory")
#define CP_WAIT(n)  asm volatile("cp.async.wait_group %0;" :: "n"(n) : "memory")

__device__ __forceinline__ void ldsm4(uint32_t* r, uint32_t addr) {
    asm volatile("ldmatrix.sync.aligned.m8n8.x4.shared.b16 {%0,%1,%2,%3}, [%4];"
                 : "=r"(r[0]), "=r"(r[1]), "=r"(r[2]), "=r"(r[3]) : "r"(addr));
}
__device__ __forceinline__ void ldsm4t(uint32_t* r, uint32_t addr) {
    asm volatile("ldmatrix.sync.aligned.m8n8.x4.trans.shared.b16 {%0,%1,%2,%3}, [%4];"
                 : "=r"(r[0]), "=r"(r[1]), "=r"(r[2]), "=r"(r[3]) : "r"(addr));
}
__device__ __forceinline__ void mma16816(float* c, const uint32_t* a, uint32_t b0, uint32_t b1) {
    asm volatile(
        "mma.sync.aligned.m16n8k16.row.col.f32.f16.f16.f32 "
        "{%0,%1,%2,%3}, {%4,%5,%6,%7}, {%8,%9}, {%0,%1,%2,%3};"
        : "+f"(c[0]), "+f"(c[1]), "+f"(c[2]), "+f"(c[3])
        : "r"(a[0]), "r"(a[1]), "r"(a[2]), "r"(a[3]), "r"(b0), "r"(b1));
}
__device__ __forceinline__ uint32_t pack_h2(float a, float b) {
    __half2 t = __floats2half2_rn(a, b);
    return *reinterpret_cast<uint32_t*>(&t);
}
#define SWZ(o) ((o) ^ (((o) >> 3) & 0x70))

// ---------------- tiny: reset expert counters ----------------
__global__ void reset_cnt() {
    if (threadIdx.x < NEXP) g_cnt[threadIdx.x] = 0;
}

// ================= fused prep kernel =================
// blocks [0,512)            : gating (8 tokens/block) + fused x->fp16
// blocks [512,16896)        : W1 fp32->fp16 streaming convert (no transpose)
// blocks [16896,33280)      : W2 fp32->fp16 streaming convert
// blocks [33280,37376)      : zero output
__global__ void __launch_bounds__(256)
prep_kernel(const float* __restrict__ x,  const float* __restrict__ Wg,
            const float* __restrict__ bg, const float* __restrict__ W1,
            const float* __restrict__ W2, float* __restrict__ out) {
    const int b = blockIdx.x;
    const int t = threadIdx.x;

    if (b < 512) {
        // ---- gating: 1 warp/token ----
        int tok  = b * 8 + (t >> 5);
        int lane = t & 31;
        const float* xr = x + (size_t)tok * DIM;
        __half* xo = g_x + (size_t)tok * DIM;
        float acc[NEXP];
#pragma unroll
        for (int e = 0; e < NEXP; e++) acc[e] = 0.f;
        for (int d = lane * 2; d < DIM; d += 64) {
            float2 xv = *reinterpret_cast<const float2*>(xr + d);
            *reinterpret_cast<uint32_t*>(xo + d) = pack_h2(xv.x, xv.y);
            const float* wr0 = Wg + d * NEXP;
#pragma unroll
            for (int e = 0; e < NEXP; e++) acc[e] += xv.x * wr0[e];
            const float* wr1 = Wg + (d + 1) * NEXP;
#pragma unroll
            for (int e = 0; e < NEXP; e++) acc[e] += xv.y * wr1[e];
        }
#pragma unroll
        for (int off = 16; off; off >>= 1)
#pragma unroll
            for (int e = 0; e < NEXP; e++)
                acc[e] += __shfl_xor_sync(0xffffffffu, acc[e], off);
        if (lane == 0) {
            float logit[NEXP], m = -1e30f;
#pragma unroll
            for (int e = 0; e < NEXP; e++) { logit[e] = acc[e] + bg[e]; m = fmaxf(m, logit[e]); }
            float p[NEXP], s = 0.f;
#pragma unroll
            for (int e = 0; e < NEXP; e++) { p[e] = expf(logit[e] - m); s += p[e]; }
            float inv = 1.f / s;
#pragma unroll
            for (int e = 0; e < NEXP; e++) p[e] *= inv;
            int e0 = 0;
#pragma unroll
            for (int e = 1; e < NEXP; e++) if (p[e] > p[e0]) e0 = e;
            int e1 = (e0 == 0) ? 1 : 0;
#pragma unroll
            for (int e = 0; e < NEXP; e++) if (e != e0 && p[e] > p[e1]) e1 = e;
            g_wgt[2 * tok + 0] = p[e0];
            g_wgt[2 * tok + 1] = p[e1];
            int p0 = atomicAdd(&g_cnt[e0], 1); g_list[e0][p0] = 2 * tok + 0;
            int p1 = atomicAdd(&g_cnt[e1], 1); g_list[e1][p1] = 2 * tok + 1;
        }
    } else if (b < 33280) {
        // ---- streaming fp32 -> fp16 convert (identity layout) ----
        const bool isW1 = b < 16896;
        const float* src = isW1 ? W1 : W2;
        __half* dst = isW1 ? g_w1 : g_w2;
        size_t i = ((size_t)(b - (isW1 ? 512 : 16896)) * 256 + t) * 8;
        float v[8];
        *reinterpret_cast<float4*>(v)     = *reinterpret_cast<const float4*>(src + i);
        *reinterpret_cast<float4*>(v + 4) = *reinterpret_cast<const float4*>(src + i + 4);
        uint32_t p[4];
#pragma unroll
        for (int j = 0; j < 4; j++) p[j] = pack_h2(v[2 * j], v[2 * j + 1]);
        *reinterpret_cast<uint4*>(dst + i) = make_uint4(p[0], p[1], p[2], p[3]);
    } else {
        size_t i = ((size_t)(b - 33280) * 256 + t) * 4;
        *reinterpret_cast<float4*>(out + i) = make_float4(0.f, 0.f, 0.f, 0.f);
    }
}

// ---------------- phase1: 128x128 CTA, warps 4m x 2n; B native [K][N] -----------
__global__ void __launch_bounds__(256, 2)
moe_gemm1(const float* __restrict__ bias) {
    constexpr int KD  = DIM;    // 1024
    constexpr int ND  = HID;    // 4096
    constexpr int NCH = KD / 128;
    constexpr int STG = 64 * 1024;  // [A0 16K][A1 16K][Bhalf0 16K][Bhalf1 16K]

    const __half* A = g_x;
    const __half* B = g_w1;

    const int e   = blockIdx.z;
    const int cnt = g_cnt[e];
    const int m0  = blockIdx.y * 128;
    if (m0 >= cnt) return;
    const int n0  = blockIdx.x * 128;
    const int tid = threadIdx.x;

    extern __shared__ char smraw[];
    char* tilep = (char*)(((uintptr_t)smraw + 1023) & ~(uintptr_t)1023);
    const uint32_t sbase = smem_u32(tilep);
    __shared__ float s_bias[128];
    if (tid < 128) s_bias[tid] = bias[(size_t)e * ND + n0 + tid];

    // ---- A load mapping (rows = gathered tokens, 128B k-subrows) ----
    const int seg = tid & 7;
    const int rg  = tid >> 3;
    uint32_t aoff[4], avalid[4], swza[4];
#pragma unroll
    for (int p = 0; p < 4; p++) {
        int r   = rg + 32 * p;
        int idx = m0 + r;
        int a   = (idx < cnt) ? g_list[e][idx] : 0;
        avalid[p] = (idx < cnt) ? 16u : 0u;
        aoff[p]   = (uint32_t)(a >> 1) * KD + seg * 8;
        swza[p]   = SWZ(r * 128 + seg * 16);
    }
    // ---- B load mapping (rows = k, 256B rows split into two 128B n-halves) ----
    const int bs  = tid & 15;        // 16B seg within 256B row
    const int brg = tid >> 4;        // 16 k-rows per pass
    uint32_t boff[8], swzb[8];
#pragma unroll
    for (int p = 0; p < 8; p++) {
        int kr  = brg + 16 * p;
        boff[p] = ((uint32_t)e * KD + kr) * ND + n0 + bs * 8;
        swzb[p] = (bs >> 3) * 16384 + SWZ(kr * 128 + (bs & 7) * 16);
    }

    // ---- fragment addressing ----
    const int lane = tid & 31;
    const int wid  = tid >> 5;
    const int wm   = wid >> 1;
    const int wn   = wid & 1;
    uint32_t abase[2], axor[2];
#pragma unroll
    for (int mf = 0; mf < 2; mf++) {
        int row   = wm * 32 + mf * 16 + (lane & 15);
        abase[mf] = row * 128 + (lane >> 4) * 16;
        axor[mf]  = (row & 7) << 4;
    }
    // B frag: k-row = lane&15, chunk16 = 2p + (lane>>4), XOR by (k&7)
    uint32_t bfr[4];
#pragma unroll
    for (int p = 0; p < 4; p++)
        bfr[p] = (lane & 15) * 128 +
                 ((((uint32_t)(2 * p + (lane >> 4))) * 16) ^ ((lane & 7) << 4));
    const uint32_t bhalf = wn * 16384;

    float acc[2][8][4];
#pragma unroll
    for (int i = 0; i < 2; i++)
#pragma unroll
        for (int j = 0; j < 8; j++)
#pragma unroll
            for (int q = 0; q < 4; q++) acc[i][j][q] = 0.f;

#define ISSUE_CHUNK1(CC, BUF) do {                                             \
        const uint32_t _koA = (uint32_t)(CC) * 128;                            \
        const uint32_t _koB = (uint32_t)(CC) * 128 * ND;                       \
        uint32_t _sb = sbase + (BUF) * STG;                                    \
        _Pragma("unroll")                                                      \
        for (int s = 0; s < 2; s++)                                            \
            _Pragma("unroll")                                                  \
            for (int p = 0; p < 4; p++)                                        \
                cp16(_sb + s * 16384 + swza[p],                                \
                     A + aoff[p] + _koA + s * 64, avalid[p]);                  \
        _Pragma("unroll")                                                      \
        for (int p = 0; p < 8; p++)                                            \
            cp16(_sb + 32768 + swzb[p], B + boff[p] + _koB, 16u);              \
        CP_COMMIT();                                                           \
    } while (0)

    ISSUE_CHUNK1(0, 0);

    for (int c = 0; c < NCH; ++c) {
        if (c + 1 < NCH) {
            ISSUE_CHUNK1(c + 1, (c + 1) & 1);
            CP_WAIT(1);
        } else {
            CP_WAIT(0);
        }
        __syncthreads();

        const uint32_t sb = sbase + (c & 1) * STG;
        const uint32_t bb_base = sb + 32768 + bhalf;
#pragma unroll
        for (int kk = 0; kk < 8; kk++) {
            const uint32_t subA = (kk >> 2) * 16384;
            const uint32_t k4   = (kk & 3) * 32;
            uint32_t ah[2][4], bb[4][4];
#pragma unroll
            for (int mf = 0; mf < 2; mf++)
                ldsm4(ah[mf], sb + subA + ((abase[mf] + k4) ^ axor[mf]));
#pragma unroll
            for (int p = 0; p < 4; p++)
                ldsm4t(bb[p], bb_base + kk * 2048 + bfr[p]);
#pragma unroll
            for (int mf = 0; mf < 2; mf++)
#pragma unroll
                for (int p = 0; p < 4; p++) {
                    mma16816(acc[mf][2 * p],     ah[mf], bb[p][0], bb[p][1]);
                    mma16816(acc[mf][2 * p + 1], ah[mf], bb[p][2], bb[p][3]);
                }
        }
        __syncthreads();
    }
#undef ISSUE_CHUNK1

    const int quad  = lane >> 2;
    const int qid   = lane & 3;
    const int ncol0 = wn * 64;

#pragma unroll
    for (int mf = 0; mf < 2; mf++) {
#pragma unroll
        for (int rv = 0; rv < 2; rv++) {
            int midx = m0 + wm * 32 + mf * 16 + rv * 8 + quad;
            if (midx >= cnt) continue;
            int a = g_list[e][midx];
            __half* dh = g_h + (size_t)a * HID + n0;
#pragma unroll
            for (int nf = 0; nf < 8; nf++) {
                int nloc = ncol0 + nf * 8 + 2 * qid;
                float v0 = fmaxf(acc[mf][nf][2 * rv]     + s_bias[nloc],     0.f);
                float v1 = fmaxf(acc[mf][nf][2 * rv + 1] + s_bias[nloc + 1], 0.f);
                *reinterpret_cast<uint32_t*>(dh + nloc) = pack_h2(v0, v1);
            }
        }
    }
}

// ---------------- phase2: 64x64 CTA, warps 4m x 2n; B native [K][N] ----------------
__global__ void __launch_bounds__(256, 2)
moe_gemm2(const float* __restrict__ bias, float* __restrict__ out) {
    constexpr int KD  = HID;    // 4096
    constexpr int ND  = DIM;    // 1024
    constexpr int NCH = KD / 128;
    constexpr int STG = 32 * 1024;   // [A0 8K][A1 8K][B 16K]

    const __half* A = g_h;
    const __half* B = g_w2;

    const int e   = blockIdx.z;
    const int cnt = g_cnt[e];
    const int m0  = blockIdx.y * 64;
    if (m0 >= cnt) return;
    const int n0  = blockIdx.x * 64;
    const int tid = threadIdx.x;

    extern __shared__ char smraw[];
    char* tilep = (char*)(((uintptr_t)smraw + 1023) & ~(uintptr_t)1023);
    const uint32_t sbase = smem_u32(tilep);
    __shared__ float s_bias[64];
    if (tid < 64) s_bias[tid] = bias[(size_t)e * ND + n0 + tid];

    const int seg = tid & 7;
    const int rg  = tid >> 3;
    uint32_t aoff[2], avalid[2], swza[2];
#pragma unroll
    for (int p = 0; p < 2; p++) {
        int r   = rg + 32 * p;
        int idx = m0 + r;
        int a   = (idx < cnt) ? g_list[e][idx] : 0;
        avalid[p] = (idx < cnt) ? 16u : 0u;
        aoff[p]   = (uint32_t)a * KD + seg * 8;
        swza[p]   = SWZ(r * 128 + seg * 16);
    }
    // B: 128 k-rows x 64n (128B rows)
    uint32_t boff[4], swzb[4];
#pragma unroll
    for (int p = 0; p < 4; p++) {
        int kr  = rg + 32 * p;
        boff[p] = ((uint32_t)e * KD + kr) * ND + n0 + seg * 8;
        swzb[p] = SWZ(kr * 128 + seg * 16);
    }

    const int lane = tid & 31;
    const int wid  = tid >> 5;
    const int wm   = wid >> 1;
    const int wn   = wid & 1;
    uint32_t abase, axor;
    {
        int row = wm * 16 + (lane & 15);
        abase   = row * 128 + (lane >> 4) * 16;
        axor    = (row & 7) << 4;
    }
    uint32_t bfr[2];
#pragma unroll
    for (int p = 0; p < 2; p++)
        bfr[p] = (lane & 15) * 128 +
                 ((((uint32_t)(4 * wn + 2 * p + (lane >> 4))) * 16) ^ ((lane & 7) << 4));

    float acc[4][4];
#pragma unroll
    for (int j = 0; j < 4; j++)
#pragma unroll
        for (int q = 0; q < 4; q++) acc[j][q] = 0.f;

#define ISSUE_CHUNK2(CC, BUF) do {                                             \
        const uint32_t _koA = (uint32_t)(CC) * 128;                            \
        const uint32_t _koB = (uint32_t)(CC) * 128 * ND;                       \
        uint32_t _sb = sbase + (BUF) * STG;                                    \
        _Pragma("unroll")                                                      \
        for (int s = 0; s < 2; s++)                                            \
            _Pragma("unroll")                                                  \
            for (int p = 0; p < 2; p++)                                        \
                cp16(_sb + s * 8192 + swza[p],                                 \
                     A + aoff[p] + _koA + s * 64, avalid[p]);                  \
        _Pragma("unroll")                                                      \
        for (int p = 0; p < 4; p++)                                            \
            cp16(_sb + 16384 + swzb[p], B + boff[p] + _koB, 16u);              \
        CP_COMMIT();                                                           \
    } while (0)

    ISSUE_CHUNK2(0, 0);

    for (int c = 0; c < NCH; ++c) {
        if (c + 1 < NCH) {
            ISSUE_CHUNK2(c + 1, (c + 1) & 1);
            CP_WAIT(1);
        } else {
            CP_WAIT(0);
        }
        __syncthreads();

        const uint32_t sb = sbase + (c & 1) * STG;
        const uint32_t bb_base = sb + 16384;
#pragma unroll
        for (int kk = 0; kk < 8; kk++) {
            const uint32_t subA = (kk >> 2) * 8192;
            const uint32_t k4   = (kk & 3) * 32;
            uint32_t ah[4], bb[2][4];
            ldsm4(ah, sb + subA + ((abase + k4) ^ axor));
#pragma unroll
            for (int p = 0; p < 2; p++)
                ldsm4t(bb[p], bb_base + kk * 2048 + bfr[p]);
#pragma unroll
            for (int p = 0; p < 2; p++) {
                mma16816(acc[2 * p],     ah, bb[p][0], bb[p][1]);
                mma16816(acc[2 * p + 1], ah, bb[p][2], bb[p][3]);
            }
        }
        __syncthreads();
    }
#undef ISSUE_CHUNK2

    const int quad  = lane >> 2;
    const int qid   = lane & 3;
    const int ncol0 = wn * 32;

#pragma unroll
    for (int rv = 0; rv < 2; rv++) {
        int midx = m0 + wm * 16 + rv * 8 + quad;
        if (midx >= cnt) continue;
        int a = g_list[e][midx];
        float w = g_wgt[a];
        float* op = out + (size_t)(a >> 1) * DIM + n0;
#pragma unroll
        for (int nf = 0; nf < 4; nf++) {
            int nloc = ncol0 + nf * 8 + 2 * qid;
            atomicAdd(op + nloc,     (acc[nf][2 * rv]     + s_bias[nloc])     * w);
            atomicAdd(op + nloc + 1, (acc[nf][2 * rv + 1] + s_bias[nloc + 1]) * w);
        }
    }
}

// ---------------- launch (sequential; no streams, no events) ----------------
extern "C" void kernel_launch(void* const* d_in, const int* in_sizes, int n_in,
                              void* d_out, int out_size) {
    const float* x  = (const float*)d_in[0];
    const float* Wg = (const float*)d_in[1];
    const float* bg = (const float*)d_in[2];
    const float* W1 = (const float*)d_in[3];
    const float* b1 = (const float*)d_in[4];
    const float* W2 = (const float*)d_in[5];
    const float* b2 = (const float*)d_in[6];
    float* out = (float*)d_out;

    const int SMEM1 = 2 * 64 * 1024 + 1024;
    const int SMEM2 = 2 * 32 * 1024 + 1024;
    cudaFuncSetAttribute((const void*)moe_gemm1,
                         cudaFuncAttributeMaxDynamicSharedMemorySize, SMEM1);
    cudaFuncSetAttribute((const void*)moe_gemm2,
                         cudaFuncAttributeMaxDynamicSharedMemorySize, SMEM2);

    reset_cnt<<<1, 32>>>();
    prep_kernel<<<37376, 256>>>(x, Wg, bg, W1, W2, out);
    moe_gemm1<<<dim3(HID / 128, MAXA / 128, NEXP), 256, SMEM1>>>(b1);
    moe_gemm2<<<dim3(DIM / 64, MAXA / 64, NEXP), 256, SMEM2>>>(b2, out);
}